// round 15
// baseline (speedup 1.0000x reference)
#include <cuda_runtime.h>
#include <cuda_bf16.h>
#include <math.h>
#include <stdint.h>

#define H 16
#define D 64
#define L 8192
#define M 128
#define NBLK 256
#define T 25
#define NCH 32

#define PADW 72     // kvW bf16 smem row halfs (prologue, 144 B rows)
#define KROWB 272   // K tf32 smem row bytes (68 floats)
#define VROWB 144   // Vt tf32 smem row bytes (36 floats)

__device__ float g_km[H*D];
__device__ float g_pq[H*M*D];
__device__ float g_pk[H*NBLK*D];
__device__ int   g_lut[H*M*T];
__device__ float g_kv_part[NCH*H*D*D];
__device__ float g_ks_part[NCH*H*D];
__device__ float g_ksum[H*D];
__device__ __nv_bfloat16 g_kvWh[H*D*D];   // (kvsum@W^T)^T split hi, [j][d]
__device__ __nv_bfloat16 g_kvWl[H*D*D];
// tf32 (rna-rounded fp32) tiles, dense: K block 32x64, Vt block 64x32
__device__ float g_kct[(size_t)H*NBLK*2048];
__device__ float g_vtt[(size_t)H*NBLK*2048];

// ---------------- helpers ----------------
__device__ __forceinline__ uint32_t smem_u32(const void* p) {
    return (uint32_t)__cvta_generic_to_shared(p);
}
__device__ __forceinline__ void cp16(uint32_t saddr, const void* gaddr) {
    asm volatile("cp.async.cg.shared.global [%0], [%1], 16;" :: "r"(saddr), "l"(gaddr));
}
#define CP_COMMIT() asm volatile("cp.async.commit_group;" ::: "memory")
#define CP_WAIT(n)  asm volatile("cp.async.wait_group %0;" :: "n"(n) : "memory")

__device__ __forceinline__ void mma16816(float* c, const uint32_t* a, uint32_t b0, uint32_t b1) {
    asm volatile(
        "mma.sync.aligned.m16n8k16.row.col.f32.bf16.bf16.f32 "
        "{%0,%1,%2,%3}, {%4,%5,%6,%7}, {%8,%9}, {%0,%1,%2,%3};"
        : "+f"(c[0]), "+f"(c[1]), "+f"(c[2]), "+f"(c[3])
        : "r"(a[0]), "r"(a[1]), "r"(a[2]), "r"(a[3]), "r"(b0), "r"(b1));
}
__device__ __forceinline__ void mmatf32(float* c, const uint32_t* a, uint32_t b0, uint32_t b1) {
    asm volatile(
        "mma.sync.aligned.m16n8k8.row.col.f32.tf32.tf32.f32 "
        "{%0,%1,%2,%3}, {%4,%5,%6,%7}, {%8,%9}, {%0,%1,%2,%3};"
        : "+f"(c[0]), "+f"(c[1]), "+f"(c[2]), "+f"(c[3])
        : "r"(a[0]), "r"(a[1]), "r"(a[2]), "r"(a[3]), "r"(b0), "r"(b1));
}
__device__ __forceinline__ void ldmx4(uint32_t& r0, uint32_t& r1, uint32_t& r2, uint32_t& r3,
                                      uint32_t addr) {
    asm volatile("ldmatrix.sync.aligned.m8n8.x4.shared.b16 {%0,%1,%2,%3}, [%4];"
                 : "=r"(r0), "=r"(r1), "=r"(r2), "=r"(r3) : "r"(addr));
}
__device__ __forceinline__ uint32_t f2tf32(float x) {
    uint32_t r;
    asm("cvt.rna.tf32.f32 %0, %1;" : "=r"(r) : "f"(x));
    return r;
}
__device__ __forceinline__ void split_pair(float a, float b, uint32_t& hi, uint32_t& lo) {
    __nv_bfloat16 ha = __float2bfloat16(a);
    __nv_bfloat16 hb = __float2bfloat16(b);
    __nv_bfloat162 hp; hp.x = ha; hp.y = hb;
    __nv_bfloat162 lp; lp.x = __float2bfloat16(a - __bfloat162float(ha));
    lp.y = __float2bfloat16(b - __bfloat162float(hb));
    hi = *(uint32_t*)&hp; lo = *(uint32_t*)&lp;
}

// ===== prep: pooled_q (y<M), pooled_k uncentered (y>=M); k read ONCE =====
__global__ __launch_bounds__(256) void prep_kernel(const float* __restrict__ q,
                                                   const float* __restrict__ k) {
    int h = blockIdx.x, y = blockIdx.y;
    int tid = threadIdx.x;
    __shared__ float part[256];
    int d = tid & 63, sub = tid >> 6;
    if (y < M) {
        float s = 0.f;
        for (int i = sub; i < 64; i += 4) s += q[((y*64 + i)*H + h)*D + d];
        part[tid] = s;
        __syncthreads();
        if (tid < 64)
            g_pq[(h*M + y)*D + tid] = (part[tid] + part[tid+64] + part[tid+128] + part[tid+192]) * (1.0f/64.0f);
    } else {
        int n = y - M;
        float s = 0.f;
        for (int i = sub; i < 32; i += 4) s += k[((n*32 + i)*H + h)*D + d];
        part[tid] = s;
        __syncthreads();
        if (tid < 64)
            g_pk[(h*NBLK + n)*D + tid] = (part[tid] + part[tid+64] + part[tid+128] + part[tid+192]) * (1.0f/32.0f);
    }
}
__global__ __launch_bounds__(64) void km_from_pk_kernel() {
    int h = blockIdx.x, d = threadIdx.x;
    float s = 0.f;
    for (int n = 0; n < NBLK; n++) s += g_pk[(h*NBLK + n)*D + d];
    g_km[h*D + d] = s * (1.0f/NBLK);
}

// ===== fused score + topk =====
__global__ __launch_bounds__(256) void scoretopk_kernel() {
    int h = blockIdx.x, mg = blockIdx.y * 16;
    __shared__ float pq[16][64];
    __shared__ float kmS[64];
    __shared__ float corr[16];
    __shared__ float sc[16][NBLK];
    int tid = threadIdx.x;
    for (int i = tid; i < 16*64; i += 256)
        pq[i >> 6][i & 63] = g_pq[(h*M + mg + (i >> 6))*D + (i & 63)];
    if (tid < 64) kmS[tid] = g_km[h*D + tid];
    __syncthreads();
    if (tid < 16) {
        float s = 0.f;
        #pragma unroll
        for (int d = 0; d < 64; d++) s += pq[tid][d] * kmS[d];
        corr[tid] = s;
    }
    __syncthreads();
    const float4* pk = (const float4*)(g_pk + (h*NBLK + tid)*D);
    float acc[16];
    #pragma unroll
    for (int mm = 0; mm < 16; mm++) acc[mm] = 0.f;
    #pragma unroll
    for (int ch = 0; ch < 4; ch++) {
        float4 kv[4];
        #pragma unroll
        for (int i = 0; i < 4; i++) kv[i] = pk[ch*4 + i];
        #pragma unroll
        for (int mm = 0; mm < 16; mm++) {
            float s = 0.f;
            #pragma unroll
            for (int i = 0; i < 4; i++) {
                float4 qv = *(const float4*)(&pq[mm][ch*16 + i*4]);
                s += qv.x*kv[i].x + qv.y*kv[i].y + qv.z*kv[i].z + qv.w*kv[i].w;
            }
            acc[mm] += s;
        }
    }
    #pragma unroll
    for (int mm = 0; mm < 16; mm++) sc[mm][tid] = acc[mm] - corr[mm];
    __syncthreads();
    int w = tid >> 5, lane = tid & 31;
    for (int s2 = 0; s2 < 2; s2++) {
        int mloc = w*2 + s2;
        float v[8];
        #pragma unroll
        for (int j = 0; j < 8; j++) v[j] = sc[mloc][j*32 + lane];
        int sel[T];
        for (int t = 0; t < T; t++) {
            float bv = -INFINITY; int bi = 1 << 30;
            #pragma unroll
            for (int j = 0; j < 8; j++)
                if (v[j] > bv) { bv = v[j]; bi = j*32 + lane; }
            #pragma unroll
            for (int off = 16; off > 0; off >>= 1) {
                float ov = __shfl_xor_sync(0xffffffffu, bv, off);
                int   oi = __shfl_xor_sync(0xffffffffu, bi, off);
                if (ov > bv || (ov == bv && oi < bi)) { bv = ov; bi = oi; }
            }
            sel[t] = bi;
            if ((bi & 31) == lane) v[bi >> 5] = -INFINITY;
        }
        if (lane == 0) {
            for (int a = 1; a < T; a++) {
                int key = sel[a]; int b = a - 1;
                while (b >= 0 && sel[b] > key) { sel[b+1] = sel[b]; b--; }
                sel[b+1] = key;
            }
            for (int t = 0; t < T; t++) g_lut[(h*M + mg + mloc)*T + t] = sel[t];
        }
    }
}

// ===== precompute centered K (tf32, dense 32x64) + transposed V (tf32, dense 64x32) =====
__global__ __launch_bounds__(128) void convert_kv_kernel(const float* __restrict__ k,
                                                         const float* __restrict__ v) {
    int h = blockIdx.x, n = blockIdx.y;
    int tid = threadIdx.x;
    __shared__ float vS[32][65];
    {
        int vr = tid >> 2, vp = tid & 3;
        const float4* src = (const float4*)(v + ((size_t)(n*32 + vr)*H + h)*D + vp*16);
        #pragma unroll
        for (int i = 0; i < 4; i++) {
            float4 f = src[i];
            vS[vr][vp*16 + 4*i + 0] = f.x;
            vS[vr][vp*16 + 4*i + 1] = f.y;
            vS[vr][vp*16 + 4*i + 2] = f.z;
            vS[vr][vp*16 + 4*i + 3] = f.w;
        }
    }
    {
        int kr = tid >> 2, kp = tid & 3;
        const float4* src = (const float4*)(k + ((size_t)(n*32 + kr)*H + h)*D + kp*16);
        float* dst = g_kct + ((size_t)(h*NBLK + n)*32 + kr)*64 + kp*16;
        #pragma unroll
        for (int i = 0; i < 4; i++) {
            float4 f = src[i];
            uint4 o;
            o.x = f2tf32(f.x - g_km[h*D + kp*16 + 4*i+0]);
            o.y = f2tf32(f.y - g_km[h*D + kp*16 + 4*i+1]);
            o.z = f2tf32(f.z - g_km[h*D + kp*16 + 4*i+2]);
            o.w = f2tf32(f.w - g_km[h*D + kp*16 + 4*i+3]);
            *(uint4*)(dst + 4*i) = o;
        }
    }
    __syncthreads();
    {
        int d = tid & 63, part = tid >> 6;  // part: keys 0-15 / 16-31
        float* dst = g_vtt + ((size_t)(h*NBLK + n)*64 + d)*32 + part*16;
        #pragma unroll
        for (int i = 0; i < 4; i++) {
            uint4 o;
            o.x = f2tf32(vS[part*16 + 4*i + 0][d]);
            o.y = f2tf32(vS[part*16 + 4*i + 1][d]);
            o.z = f2tf32(vS[part*16 + 4*i + 2][d]);
            o.w = f2tf32(vS[part*16 + 4*i + 3][d]);
            *(uint4*)(dst + 4*i) = o;
        }
    }
}

// ====== kvsum partials ======
__global__ __launch_bounds__(256) void kvsum_partial_kernel(const float* __restrict__ k,
                                                            const float* __restrict__ v) {
    int h = blockIdx.x, c = blockIdx.y;
    __shared__ float kfS[8][64];
    __shared__ float vS[8][64];
    int tid = threadIdx.x, w = tid >> 5, lane = tid & 31;
    int e = tid & 63, g = tid >> 6;
    int d0 = g * 16;
    float acc[16];
    #pragma unroll
    for (int j = 0; j < 16; j++) acc[j] = 0.f;
    float ks_acc = 0.f;
    for (int sIt = 0; sIt < 32; sIt++) {
        int l = c*256 + sIt*8 + w;
        __syncthreads();
        const float* kr = k + (l*H + h)*D;
        const float* vr = v + (l*H + h)*D;
        float e0 = __expf(kr[lane]), e1 = __expf(kr[lane + 32]);
        float sm = e0 + e1;
        #pragma unroll
        for (int o = 16; o > 0; o >>= 1) sm += __shfl_xor_sync(0xffffffffu, sm, o);
        float inv = 1.f / sm;
        kfS[w][lane] = e0*inv; kfS[w][lane+32] = e1*inv;
        vS[w][lane] = vr[lane]; vS[w][lane+32] = vr[lane+32];
        __syncthreads();
        #pragma unroll
        for (int rr = 0; rr < 8; rr++) {
            float ve = vS[rr][e];
            #pragma unroll
            for (int j = 0; j < 16; j++) acc[j] += kfS[rr][d0 + j] * ve;
        }
        if (g == 0) {
            #pragma unroll
            for (int rr = 0; rr < 8; rr++) ks_acc += kfS[rr][e];
        }
    }
    float* dst = g_kv_part + (c*H + h)*D*D;
    #pragma unroll
    for (int j = 0; j < 16; j++) dst[(d0 + j)*D + e] = acc[j];
    if (g == 0) g_ks_part[(c*H + h)*D + e] = ks_acc;
}

// ====== reduce partials + fold projection: kvW^T bf16 split ======
__global__ __launch_bounds__(256) void reduce_kv_kernel(const float* __restrict__ W) {
    int h = blockIdx.x;
    __shared__ float kvS[64][64];
    __shared__ float WS[64][65];
    int tid = threadIdx.x;
    for (int i = tid; i < D*D; i += 256) {
        float s = 0.f;
        for (int c = 0; c < NCH; c++) s += g_kv_part[(c*H + h)*D*D + i];
        kvS[i >> 6][i & 63] = s;
    }
    for (int i = tid; i < D*D; i += 256) WS[i >> 6][i & 63] = W[i];
    for (int i = tid; i < D; i += 256) {
        float s = 0.f;
        for (int c = 0; c < NCH; c++) s += g_ks_part[(c*H + h)*D + i];
        g_ksum[h*D + i] = s;
    }
    __syncthreads();
    int j = tid & 63, dg = tid >> 6;
    #pragma unroll
    for (int dd = 0; dd < 16; dd++) {
        int d = dg*16 + dd;
        float s = 0.f;
        #pragma unroll
        for (int e = 0; e < 64; e++) s += kvS[d][e] * WS[j][e];
        __nv_bfloat16 hi = __float2bfloat16(s);
        __nv_bfloat16 lo = __float2bfloat16(s - __bfloat162float(hi));
        g_kvWh[h*D*D + j*64 + d] = hi;
        g_kvWl[h*D*D + j*64 + d] = lo;
    }
}

// ============ fused: bf16 linear prologue + tf32 block-sparse attention ============
// smem overlay:
//   mainloop: K tf32 [2][32 rows x 272B] at 0..17408 ; Vt tf32 [2][64 rows x 144B] at 17408..35840
//   prologue: kvWh bf16 [64][PADW] at 0..9216 ; kvWl at 9216..18432
#define SMK_OFF(buf)  ((buf)*8704)
#define SMV_OFF(buf)  (17408 + (buf)*9216)

__global__ __launch_bounds__(128) void sparse_attn_mma(
    const float* __restrict__ q, const float* __restrict__ b, float* __restrict__ out)
{
    __shared__ __align__(16) char SM[35840];
    __shared__ float ksumS[64];
    __shared__ float bS[64];

    const int h = blockIdx.x, m = blockIdx.y;
    const int tid = threadIdx.x;
    const int w = tid >> 5, lane = tid & 31;
    const int g = lane >> 2, tc = lane & 3;
    const int lr = lane & 7, quad = lane >> 3;
    // bf16 prologue ldmatrix mapping (16-row tiles)
    const int rowoff16 = ((quad >> 1) << 3) + lr;
    const int koff16 = (quad & 1) << 3;
    // tf32 ldmatrix per-lane offset: row lr, matrix quad (+16B each)
    const uint32_t sbase = smem_u32(SM);
    const uint32_t laneK = (uint32_t)(lr*KROWB + quad*16);
    const uint32_t laneV = (uint32_t)(lr*VROWB + quad*16);

    const int r0 = m*64 + w*16 + g;
    float* out0 = out + ((size_t)r0*H + h)*D;
    float* out1 = out + ((size_t)(r0+8)*H + h)*D;

    // ---- kvW -> smem (bf16, [64][PADW]) ----
    {
        int r = tid >> 1, seg = tid & 1;
        uint32_t dh = sbase + (uint32_t)(r*PADW + seg*32)*2;
        uint32_t dl = sbase + 9216u + (uint32_t)(r*PADW + seg*32)*2;
        size_t src = (size_t)h*D*D + (size_t)r*64 + seg*32;
        #pragma unroll
        for (int i = 0; i < 4; i++) {
            cp16(dh + i*16, g_kvWh + src + i*8);
            cp16(dl + i*16, g_kvWl + src + i*8);
        }
        CP_COMMIT();
    }
    if (tid < 64) { ksumS[tid] = g_ksum[h*D + tid]; bS[tid] = b[tid]; }
    __syncthreads();

    // ---- Q fragments (tf32, persistent) + linear-branch E fragments (bf16) ----
    uint32_t aQ[8][4];
    uint32_t aEh[4][4], aEl[4][4];
    #pragma unroll
    for (int ri = 0; ri < 2; ri++) {
        const float* qr = q + ((size_t)(r0 + ri*8)*H + h)*D;
        float exr[16];
        float se = 0.f, sd = 0.f;
        #pragma unroll
        for (int kt = 0; kt < 4; kt++) {
            int c0 = kt*16 + tc*2;
            float2 fa = *(const float2*)(qr + c0);
            float2 fb = *(const float2*)(qr + c0 + 8);
            float e0 = __expf(fa.x), e1 = __expf(fa.y);
            float e2 = __expf(fb.x), e3 = __expf(fb.y);
            exr[kt*4+0] = e0; exr[kt*4+1] = e1; exr[kt*4+2] = e2; exr[kt*4+3] = e3;
            se += e0 + e1 + e2 + e3;
            sd += e0*ksumS[c0] + e1*ksumS[c0+1] + e2*ksumS[c0+8] + e3*ksumS[c0+9];
        }
        // tf32 Q fragments: a[kst] = {Q[g][8k+tc], Q[g+8][8k+tc], Q[g][8k+tc+4], Q[g+8][8k+tc+4]}
        #pragma unroll
        for (int kst = 0; kst < 8; kst++) {
            float qa = qr[kst*8 + tc];
            float qb = qr[kst*8 + tc + 4];
            aQ[kst][0 + ri] = f2tf32(qa);
            aQ[kst][2 + ri] = f2tf32(qb);
        }
        se += __shfl_xor_sync(0xffffffffu, se, 1);
        se += __shfl_xor_sync(0xffffffffu, se, 2);
        sd += __shfl_xor_sync(0xffffffffu, sd, 1);
        sd += __shfl_xor_sync(0xffffffffu, sd, 2);
        float scale = 1.f / (sd + 1e-6f*se);
        #pragma unroll
        for (int kt = 0; kt < 4; kt++) {
            split_pair(exr[kt*4+0]*scale, exr[kt*4+1]*scale, aEh[kt][ri],   aEl[kt][ri]);
            split_pair(exr[kt*4+2]*scale, exr[kt*4+3]*scale, aEh[kt][2+ri], aEl[kt][2+ri]);
        }
    }
    // fix aQ ordering: ri loop above filled [0/2]+ri -> a0=(g,tc),a1=(g+8,tc),a2=(g,tc+4),a3=(g+8,tc+4) ✓

    float o[8][4];
    #pragma unroll
    for (int a = 0; a < 8; a++)
        #pragma unroll
        for (int j = 0; j < 4; j++) o[a][j] = 0.f;

    // ---- linear-branch GEMM (bf16 3-pass) ----
    CP_WAIT(0);
    __syncthreads();
    {
        const uint32_t aWh = sbase + (uint32_t)(rowoff16*PADW + koff16)*2;
        const uint32_t aWl = sbase + 9216u + (uint32_t)(rowoff16*PADW + koff16)*2;
        #pragma unroll
        for (int kt = 0; kt < 4; kt++) {
            #pragma unroll
            for (int nvp = 0; nvp < 4; nvp++) {
                uint32_t off = (uint32_t)(nvp*16*PADW + kt*16)*2;
                uint32_t h0,h1,h2,h3, l0,l1,l2,l3;
                ldmx4(h0,h1,h2,h3, aWh + off);
                ldmx4(l0,l1,l2,l3, aWl + off);
                mma16816(o[2*nvp],   aEh[kt], h0, h1);
                mma16816(o[2*nvp],   aEl[kt], h0, h1);
                mma16816(o[2*nvp],   aEh[kt], l0, l1);
                mma16816(o[2*nvp+1], aEh[kt], h2, h3);
                mma16816(o[2*nvp+1], aEl[kt], h2, h3);
                mma16816(o[2*nvp+1], aEh[kt], l2, l3);
            }
        }
    }
    #pragma unroll
    for (int nv = 0; nv < 8; nv++) {
        int cc = nv*8 + tc*2;
        *(float2*)(out0 + cc) = make_float2(o[nv][0] + bS[cc], o[nv][1] + bS[cc+1]);
        *(float2*)(out1 + cc) = make_float2(o[nv][2] + bS[cc], o[nv][3] + bS[cc+1]);
        o[nv][0] = 0.f; o[nv][1] = 0.f; o[nv][2] = 0.f; o[nv][3] = 0.f;
    }
    __syncthreads();   // kvW smem reads done before K tiles overwrite

    // ---- sparse mainloop (tf32) ----
    const int krow = tid >> 2, kseg = tid & 3;   // K: row 0..31, 64B seg
    const int vrow = tid >> 1, vseg = tid & 1;   // V: row 0..63, 64B seg
    const uint32_t ksm = (uint32_t)(krow*KROWB + kseg*64);
    const uint32_t vsm = (uint32_t)(vrow*VROWB + vseg*64);
    const size_t   kgo = (size_t)krow*64 + kseg*16;
    const size_t   vgo = (size_t)vrow*32 + vseg*16;
    const int* lut = g_lut + (h*M + m)*T;

    #define LOAD_STAGE(n_, buf_) do { \
        const float* kb = g_kct + ((size_t)(h*NBLK + (n_)))*2048 + kgo; \
        const float* vb = g_vtt + ((size_t)(h*NBLK + (n_)))*2048 + vgo; \
        uint32_t sk = sbase + SMK_OFF(buf_) + ksm; \
        uint32_t sv = sbase + SMV_OFF(buf_) + vsm; \
        cp16(sk,      kb);      cp16(sk + 16, kb + 4); \
        cp16(sk + 32, kb + 8);  cp16(sk + 48, kb + 12); \
        cp16(sv,      vb);      cp16(sv + 16, vb + 4); \
        cp16(sv + 32, vb + 8);  cp16(sv + 48, vb + 12); \
    } while (0)

    float lrow0 = 0.f, lrow1 = 0.f;

    LOAD_STAGE(lut[0], 0);
    CP_COMMIT();

    for (int t = 0; t < T; t++) {
        int buf = t & 1;
        if (t + 1 < T) {
            LOAD_STAGE(lut[t+1], (t+1) & 1);
            CP_COMMIT();
            CP_WAIT(1);
        } else {
            CP_WAIT(0);
        }
        __syncthreads();

        const uint32_t aK = sbase + SMK_OFF(buf) + laneK;
        const uint32_t aV = sbase + SMV_OFF(buf) + laneV;

        // ---- QK: S[16q x 32k] single-pass tf32 ----
        float c[4][4];
        #pragma unroll
        for (int nt = 0; nt < 4; nt++)
            #pragma unroll
            for (int j = 0; j < 4; j++) c[nt][j] = 0.f;
        #pragma unroll
        for (int kp = 0; kp < 4; kp++) {       // dim pairs of 8 (16 dims)
            #pragma unroll
            for (int nt = 0; nt < 4; nt++) {   // key tiles of 8
                uint32_t b00,b01,b10,b11;
                ldmx4(b00,b01,b10,b11, aK + (uint32_t)(nt*8*KROWB + kp*64));
                mmatf32(c[nt], aQ[2*kp],   b00, b01);
                mmatf32(c[nt], aQ[2*kp+1], b10, b11);
            }
        }
        // ---- exp + row sums ----
        float pr[4][4];
        float rs0 = 0.f, rs1 = 0.f;
        #pragma unroll
        for (int nt = 0; nt < 4; nt++) {
            #pragma unroll
            for (int j = 0; j < 4; j++) pr[nt][j] = __expf(c[nt][j] * 0.125f);
            rs0 += pr[nt][0] + pr[nt][1];
            rs1 += pr[nt][2] + pr[nt][3];
        }
        rs0 += __shfl_xor_sync(0xffffffffu, rs0, 1);
        rs0 += __shfl_xor_sync(0xffffffffu, rs0, 2);
        rs1 += __shfl_xor_sync(0xffffffffu, rs1, 1);
        rs1 += __shfl_xor_sync(0xffffffffu, rs1, 2);
        lrow0 += rs0; lrow1 += rs1;

        // ---- PV: single-pass tf32, P repacked via shuffles ----
        const int srcA = (g << 2) + (tc >> 1);
        const int srcB = srcA + 2;
        const bool odd = tc & 1;
        #pragma unroll
        for (int kp = 0; kp < 2; kp++) {       // key pairs of 8 ksts (16 keys)
            uint32_t aP0[4], aP1[4];
            #pragma unroll
            for (int s2 = 0; s2 < 2; s2++) {
                const float* p = pr[2*kp + s2];
                float v0a = __shfl_sync(0xffffffffu, p[0], srcA);
                float v0b = __shfl_sync(0xffffffffu, p[1], srcA);
                float v1a = __shfl_sync(0xffffffffu, p[2], srcA);
                float v1b = __shfl_sync(0xffffffffu, p[3], srcA);
                float v2a = __shfl_sync(0xffffffffu, p[0], srcB);
                float v2b = __shfl_sync(0xffffffffu, p[1], srcB);
                float v3a = __shfl_sync(0xffffffffu, p[2], srcB);
                float v3b = __shfl_sync(0xffffffffu, p[3], srcB);
                uint32_t* dst = s2 ? aP1 : aP0;
                dst[0] = f2tf32(odd ? v0b : v0a);
                dst[1] = f2tf32(odd ? v1b : v1a);
                dst[2] = f2tf32(odd ? v2b : v2a);
                dst[3] = f2tf32(odd ? v3b : v3a);
            }
            #pragma unroll
            for (int nv = 0; nv < 8; nv++) {   // dim tiles of 8
                uint32_t b00,b01,b10,b11;
                ldmx4(b00,b01,b10,b11, aV + (uint32_t)(nv*8*VROWB + kp*64));
                mmatf32(o[nv], aP0, b00, b01);
                mmatf32(o[nv], aP1, b10, b11);
            }
        }
        __syncthreads();
    }

    // ---- epilogue: out += o_s / lrow ----
    float inv0 = 1.f / lrow0;
    float inv1 = 1.f / lrow1;
    #pragma unroll
    for (int nv = 0; nv < 8; nv++) {
        int cc = nv*8 + tc*2;
        float2 p0 = *(float2*)(out0 + cc);
        float2 p1 = *(float2*)(out1 + cc);
        p0.x += o[nv][0]*inv0; p0.y += o[nv][1]*inv0;
        p1.x += o[nv][2]*inv1; p1.y += o[nv][3]*inv1;
        *(float2*)(out0 + cc) = p0;
        *(float2*)(out1 + cc) = p1;
    }
    #undef LOAD_STAGE
}

extern "C" void kernel_launch(void* const* d_in, const int* in_sizes, int n_in,
                              void* d_out, int out_size) {
    const float* q = (const float*)d_in[0];
    const float* k = (const float*)d_in[1];
    const float* v = (const float*)d_in[2];
    const float* W = (const float*)d_in[3];
    const float* b = (const float*)d_in[4];
    float* out = (float*)d_out;

    prep_kernel<<<dim3(H, M + NBLK), 256>>>(q, k);
    km_from_pk_kernel<<<H, 64>>>();
    scoretopk_kernel<<<dim3(H, M/16), 256>>>();
    convert_kv_kernel<<<dim3(H, NBLK), 128>>>(k, v);
    kvsum_partial_kernel<<<dim3(H, NCH), 256>>>(k, v);
    reduce_kv_kernel<<<H, 256>>>(W);
    sparse_attn_mma<<<dim3(H, M), 128>>>(q, b, out);
}